// round 14
// baseline (speedup 1.0000x reference)
#include <cuda_runtime.h>
#include <cuda_fp16.h>
#include <cstdint>

#define Kk 8
#define Dd 768
#define Gg 20000
#define TOPKN 200
#define BP 256
#define NROW 2048
#define KD 6144
#define SCALE 0.03608439182435161f

// screen GEMM tiling: BM=64 x BN=160, grid (4,125)=500 CTAs, 2 CTAs/SM
#define BM 64
#define BN 160
#define NTILE_N 125
#define NCHUNK 192          // KD/32
// smem stage: A(f16) 64x64B = 4KB | B(f16) 160x64B = 10KB
#define OFF_BHS 4096
#define STG_S 14336
#define SMEM_SCREEN (2 * STG_S)

#define KMAX 1024
#define MARGIN 0.012f

__device__ float g_w[Kk];
__device__ float g_cb[BP];
__device__ float g_bqbk;
__device__ float g_r[Dd];
__device__ float g_v[Dd];
__device__ float g_M[Dd * Dd];
__device__ float g_Q2[NROW * Dd];
__device__ __half g_Ah[NROW * Dd];       // f16 hi-split of Q2 (written by gemm_Q2)
__device__ float g_qb[NROW];
__device__ float g_rowbias[BP];
__device__ float g_impact[BP * Gg];      // screen values
__device__ int   g_cand[BP * KMAX];
__device__ int   g_ncand[BP];
__device__ float g_exval[BP * KMAX];

// ---------------- helpers ----------------
__device__ __forceinline__ uint32_t smem_u32(const void* p) {
    uint32_t a;
    asm("{ .reg .u64 t; cvta.to.shared.u64 t, %1; cvt.u32.u64 %0, t; }" : "=r"(a) : "l"(p));
    return a;
}
__device__ __forceinline__ void ldsm4(uint32_t* r, uint32_t a) {
    asm volatile("ldmatrix.sync.aligned.m8n8.x4.shared.b16 {%0,%1,%2,%3}, [%4];"
                 : "=r"(r[0]), "=r"(r[1]), "=r"(r[2]), "=r"(r[3]) : "r"(a));
}
__device__ __forceinline__ void mma16816(float* c, const uint32_t* a, const uint32_t* b) {
    asm volatile("mma.sync.aligned.m16n8k16.row.col.f32.f16.f16.f32 "
                 "{%0,%1,%2,%3}, {%4,%5,%6,%7}, {%8,%9}, {%0,%1,%2,%3};"
                 : "+f"(c[0]), "+f"(c[1]), "+f"(c[2]), "+f"(c[3])
                 : "r"(a[0]), "r"(a[1]), "r"(a[2]), "r"(a[3]), "r"(b[0]), "r"(b[1]));
}
__device__ __forceinline__ void cvt_sts_hi(float4 f, uint32_t addr) {
    __half2 h01 = __floats2half2_rn(f.x, f.y);
    __half2 h23 = __floats2half2_rn(f.z, f.w);
    uint32_t h0 = *(uint32_t*)&h01, h1 = *(uint32_t*)&h23;
    asm volatile("st.shared.v2.b32 [%0], {%1,%2};" :: "r"(addr), "r"(h0), "r"(h1) : "memory");
}
__device__ __forceinline__ void sts_u2(uint2 v, uint32_t addr) {
    asm volatile("st.shared.v2.b32 [%0], {%1,%2};" :: "r"(addr), "r"(v.x), "r"(v.y) : "memory");
}
__device__ __forceinline__ unsigned int fkey(float v) {
    unsigned int u = __float_as_uint(v);
    return (u & 0x80000000u) ? ~u : (u | 0x80000000u);
}
__device__ __forceinline__ float fkey_inv(unsigned int k) {
    return (k & 0x80000000u) ? __uint_as_float(k ^ 0x80000000u) : __uint_as_float(~k);
}

// ---- merged prep + rv ----
__global__ void preprv_kernel(const float* __restrict__ conf, const float* __restrict__ fw,
                              const float* __restrict__ bq, const float* __restrict__ bk,
                              const float* __restrict__ Wq, const float* __restrict__ Wk,
                              float* __restrict__ out_w, int write_w) {
    int t = threadIdx.x;
    if (blockIdx.x < 12) {
        if (t < 128) {
            int idx = blockIdx.x * 128 + t;
            if (idx < Dd) {
                float s = 0.f;
                for (int e = 0; e < Dd; e++) s += bq[e] * Wk[e * Dd + idx];
                g_r[idx] = s;
            } else {
                int c = idx - Dd;
                float s = 0.f;
                for (int e = 0; e < Dd; e++) s += Wq[e * Dd + c] * bk[e];
                g_v[c] = s;
            }
        }
        return;
    }
    __shared__ float sw[Kk];
    __shared__ float red[256];
    if (t == 0) {
        float mx = fw[0];
        for (int k = 1; k < Kk; k++) mx = fmaxf(mx, fw[k]);
        float e[Kk]; float s = 0.f;
        for (int k = 0; k < Kk; k++) { e[k] = expf(fw[k] - mx); s += e[k]; }
        for (int k = 0; k < Kk; k++) { sw[k] = e[k] / s; g_w[k] = sw[k]; }
    }
    __syncthreads();
    float p = 0.f;
    for (int i = t; i < Dd; i += 256) p += bq[i] * bk[i];
    red[t] = p; __syncthreads();
    for (int o = 128; o > 0; o >>= 1) { if (t < o) red[t] += red[t + o]; __syncthreads(); }
    if (t == 0) g_bqbk = red[0];
    float cb = 0.f;
    for (int k = 0; k < Kk; k++) {
        float c = fmaxf(conf[t * Kk + k], 1e-6f);
        cb += logf(c) * sw[k];
    }
    g_cb[t] = cb;
    if (write_w && t < Kk) out_w[t] = sw[t];
}

// ---- M = Wq^T @ Wk ----
__global__ void __launch_bounds__(256) gemm_M_kernel(const float* __restrict__ Wq,
                                                     const float* __restrict__ Wk) {
    __shared__ float As[16][64];
    __shared__ float Bs[16][64];
    int t = threadIdx.x;
    int d0 = blockIdx.x * 64, c0 = blockIdx.y * 64;
    int tx = t & 15, ty = t >> 4;
    float hi[4][4];
    #pragma unroll
    for (int i = 0; i < 4; i++)
        #pragma unroll
        for (int j = 0; j < 4; j++) hi[i][j] = 0.f;
    int lkk = (t * 4) >> 6, lm = (t * 4) & 63;
    for (int e0 = 0; e0 < Dd; e0 += 16) {
        float4 a = *(const float4*)(Wq + (e0 + lkk) * Dd + c0 + lm);
        float4 b = *(const float4*)(Wk + (e0 + lkk) * Dd + d0 + lm);
        __syncthreads();
        *(float4*)&As[lkk][lm] = a;
        *(float4*)&Bs[lkk][lm] = b;
        __syncthreads();
        float tv[4][4];
        #pragma unroll
        for (int i = 0; i < 4; i++)
            #pragma unroll
            for (int j = 0; j < 4; j++) tv[i][j] = 0.f;
        #pragma unroll
        for (int kk = 0; kk < 16; kk++) {
            float4 av = *(const float4*)&As[kk][ty * 4];
            float4 bv = *(const float4*)&Bs[kk][tx * 4];
            float am[4] = {av.x, av.y, av.z, av.w};
            float bn[4] = {bv.x, bv.y, bv.z, bv.w};
            #pragma unroll
            for (int i = 0; i < 4; i++)
                #pragma unroll
                for (int j = 0; j < 4; j++) tv[i][j] = fmaf(am[i], bn[j], tv[i][j]);
        }
        #pragma unroll
        for (int i = 0; i < 4; i++)
            #pragma unroll
            for (int j = 0; j < 4; j++) hi[i][j] += tv[i][j];
    }
    #pragma unroll
    for (int i = 0; i < 4; i++)
        #pragma unroll
        for (int j = 0; j < 4; j++)
            g_M[(c0 + ty * 4 + i) * Dd + d0 + tx * 4 + j] = hi[i][j];
}

// ---- Q2 = w_k * (ctxQ @ M + r); also writes f16 hi-split for the screen ----
__global__ void __launch_bounds__(256) gemm_Q2_kernel(const float* __restrict__ ctxQ) {
    __shared__ float As[16][68];
    __shared__ float Bs[16][64];
    int t = threadIdx.x;
    int d0 = blockIdx.x * 64, m0 = blockIdx.y * 64;
    int tx = t & 15, ty = t >> 4;
    float hi[4][4];
    #pragma unroll
    for (int i = 0; i < 4; i++)
        #pragma unroll
        for (int j = 0; j < 4; j++) hi[i][j] = 0.f;
    int alm = (t * 4) >> 4;
    int akk = (t * 4) & 15;
    int bkk = (t * 4) >> 6, bn = (t * 4) & 63;
    for (int e0 = 0; e0 < Dd; e0 += 16) {
        float4 a = *(const float4*)(ctxQ + (m0 + alm) * Dd + e0 + akk);
        float4 b = *(const float4*)(g_M + (e0 + bkk) * Dd + d0 + bn);
        __syncthreads();
        As[akk + 0][alm] = a.x; As[akk + 1][alm] = a.y;
        As[akk + 2][alm] = a.z; As[akk + 3][alm] = a.w;
        *(float4*)&Bs[bkk][bn] = b;
        __syncthreads();
        float tv[4][4];
        #pragma unroll
        for (int i = 0; i < 4; i++)
            #pragma unroll
            for (int j = 0; j < 4; j++) tv[i][j] = 0.f;
        #pragma unroll
        for (int kk = 0; kk < 16; kk++) {
            float4 av = *(const float4*)&As[kk][ty * 4];
            float4 bv = *(const float4*)&Bs[kk][tx * 4];
            float am[4] = {av.x, av.y, av.z, av.w};
            float bn2[4] = {bv.x, bv.y, bv.z, bv.w};
            #pragma unroll
            for (int i = 0; i < 4; i++)
                #pragma unroll
                for (int j = 0; j < 4; j++) tv[i][j] = fmaf(am[i], bn2[j], tv[i][j]);
        }
        #pragma unroll
        for (int i = 0; i < 4; i++)
            #pragma unroll
            for (int j = 0; j < 4; j++) hi[i][j] += tv[i][j];
    }
    #pragma unroll
    for (int i = 0; i < 4; i++) {
        int m = m0 + ty * 4 + i;
        float wk = g_w[m & 7];
        #pragma unroll
        for (int j = 0; j < 4; j++) {
            int d = d0 + tx * 4 + j;
            float v = wk * (hi[i][j] + g_r[d]);
            g_Q2[m * Dd + d] = v;
            g_Ah[m * Dd + d] = __float2half_rn(v);
        }
    }
}

__global__ void qb_kernel(const float* __restrict__ ctxQ) {
    int w = (blockIdx.x * blockDim.x + threadIdx.x) >> 5;
    int lane = threadIdx.x & 31;
    if (w >= NROW) return;
    const float* rowp = ctxQ + w * Dd;
    float s = 0.f;
    for (int c = lane; c < Dd; c += 32) s += rowp[c] * g_v[c];
    #pragma unroll
    for (int o = 16; o > 0; o >>= 1) s += __shfl_xor_sync(0xFFFFFFFFu, s, o);
    if (lane == 0) g_qb[w] = g_w[w & 7] * (s + g_bqbk);
}

__global__ void rowbias_kernel() {
    int t = threadIdx.x;
    if (t < BP) {
        float s = 0.f;
        for (int k = 0; k < Kk; k++) s += g_qb[t * Kk + k];
        g_rowbias[t] = g_cb[t] + SCALE * s;
    }
}

// ---- screen GEMM: hh product only, BM=64 x BN=160, 2 CTAs/SM (low-reg design).
// Loads for chunk s+1 issued BEFORE the MMA phase of s (latency hidden under MMA
// + peer CTA). One barrier per chunk. Per-(m,n) HMMA accumulation sequence is
// identical to R11/R13 -> bit-identical screen values.
__global__ void __launch_bounds__(256, 2) screen_gemm(const float* __restrict__ Bg) {
    extern __shared__ char smem[];
    uint32_t sb = smem_u32(smem);
    int t = threadIdx.x, lane = t & 31, wid = t >> 5;
    int wr = wid & 3, wc = wid >> 2;      // warp tile: 16 m x 80 n
    int m0 = blockIdx.x * BM, n0 = blockIdx.y * BN;

    uint32_t offA[2], offB[5][2];
    #pragma unroll
    for (int ks = 0; ks < 2; ks++) {
        int r = wr * 16 + (lane & 15);
        int u = ks * 2 + (lane >> 4);
        offA[ks] = r * 64 + ((u ^ ((r >> 1) & 3)) << 4);
    }
    #pragma unroll
    for (int ng = 0; ng < 5; ng++)
        #pragma unroll
        for (int ks = 0; ks < 2; ks++) {
            int r = wc * 80 + ng * 16 + (lane & 7) + ((lane >> 4) << 3);
            int u = ks * 2 + ((lane >> 3) & 1);
            offB[ng][ks] = r * 64 + ((u ^ ((r >> 1) & 3)) << 4);
        }

    float C[10][4];
    #pragma unroll
    for (int j = 0; j < 10; j++)
        #pragma unroll
        for (int q = 0; q < 4; q++) C[j][q] = 0.f;

    // slot plan: slot0 (all threads) = B slot t (row t>>1, half t&1).
    // slot1: t<64 -> B slot 256+t (rows 128..159); 64<=t<192 -> A slot t-64.
    int b0row = t >> 1, b0kh = t & 1;
    bool hasB1 = (t < 64);
    int b1row = 128 + (t >> 1);
    bool hasA = (t >= 64) && (t < 192);
    int aslot = hasA ? (t - 64) : 0;
    int arow = aslot >> 1, akh = aslot & 1;
    const float* pB0 = Bg + (size_t)(n0 + b0row) * KD + b0kh * 16;
    const float* pB1 = Bg + (size_t)(n0 + (hasB1 ? b1row : 128)) * KD + b0kh * 16;
    const __half* pA = g_Ah + (size_t)(m0 + arow) * KD + akh * 16;
    // compact swizzle state (addresses computed inline per store)
    uint32_t b0base = (uint32_t)b0row * 64, b0sw = (b0row >> 1) & 3, b0kt = (uint32_t)b0kh * 2;
    uint32_t b1base = (uint32_t)b1row * 64, b1sw = (b1row >> 1) & 3;
    uint32_t abase = (uint32_t)arow * 64, asw = (arow >> 1) & 3, akt = (uint32_t)akh * 2;

    float4 pvB0[2], pvB1[2];
    uint2 pvA[2];
#define SLOADC(s) { \
    _Pragma("unroll") \
    for (int i = 0; i < 2; i++) { \
        pvB0[i] = *(const float4*)(pB0 + (s) * 32 + i * 8); \
        pvB0[i].x = pvB0[i].x; \
    } \
    { float4 e0 = *(const float4*)(pB0 + (s) * 32 + 4); \
      float4 e1 = *(const float4*)(pB0 + (s) * 32 + 12); \
      pvB1[0] = e0; pvB1[1] = e1; } \
    }
#undef SLOADC
    // full loads: 4x float4 for B0; B1/A conditional
    float4 vB0[4], vB1[4];
    uint2 vA[4];
#define SLOADC(s) { \
    _Pragma("unroll") \
    for (int i = 0; i < 4; i++) vB0[i] = *(const float4*)(pB0 + (s) * 32 + i * 4); \
    if (hasB1) { \
        _Pragma("unroll") \
        for (int i = 0; i < 4; i++) vB1[i] = *(const float4*)(pB1 + (s) * 32 + i * 4); \
    } else if (hasA) { \
        _Pragma("unroll") \
        for (int i = 0; i < 4; i++) vA[i] = *(const uint2*)(pA + (s) * 32 + i * 4); \
    } }
#define SCVTST(stg) { \
    uint32_t base_ = sb + (stg) * STG_S; \
    _Pragma("unroll") \
    for (int i = 0; i < 4; i++) { \
        uint32_t ad = base_ + OFF_BHS + b0base + (((b0kt + (i >> 1)) ^ b0sw) << 4) + (i & 1) * 8; \
        cvt_sts_hi(vB0[i], ad); \
    } \
    if (hasB1) { \
        _Pragma("unroll") \
        for (int i = 0; i < 4; i++) { \
            uint32_t ad = base_ + OFF_BHS + b1base + (((b0kt + (i >> 1)) ^ b1sw) << 4) + (i & 1) * 8; \
            cvt_sts_hi(vB1[i], ad); \
        } \
    } else if (hasA) { \
        _Pragma("unroll") \
        for (int i = 0; i < 4; i++) { \
            uint32_t ad = base_ + abase + (((akt + (i >> 1)) ^ asw) << 4) + (i & 1) * 8; \
            sts_u2(vA[i], ad); \
        } \
    } }

    SLOADC(0);
    SCVTST(0);
    __syncthreads();

    #pragma unroll 1
    for (int s = 0; s < NCHUNK; s++) {
        int cur = s & 1;
        uint32_t base = sb + cur * STG_S;
        if (s < NCHUNK - 1) SLOADC(s + 1);   // issue loads; consumed after MMA
        #pragma unroll
        for (int ks = 0; ks < 2; ks++) {
            uint32_t ah[4];
            ldsm4(ah, base + offA[ks]);
            uint32_t bh[10][2];
            #pragma unroll
            for (int ng = 0; ng < 5; ng++) {
                uint32_t rr[4];
                ldsm4(rr, base + OFF_BHS + offB[ng][ks]);
                bh[2 * ng][0] = rr[0]; bh[2 * ng][1] = rr[1];
                bh[2 * ng + 1][0] = rr[2]; bh[2 * ng + 1][1] = rr[3];
            }
            #pragma unroll
            for (int nt = 0; nt < 10; nt++) mma16816(C[nt], ah, bh[nt]);
        }
        if (s < NCHUNK - 1) SCVTST(1 - cur);
        __syncthreads();
    }

    int gid = lane >> 2, tig = lane & 3;
    int mA = m0 + wr * 16 + gid;
    float rbA = g_rowbias[mA];
    float rbB = g_rowbias[mA + 8];
    #pragma unroll
    for (int nt = 0; nt < 10; nt++) {
        int n = n0 + wc * 80 + nt * 8 + tig * 2;
        float2 v0 = make_float2(SCALE * C[nt][0] + rbA, SCALE * C[nt][1] + rbA);
        float2 v1 = make_float2(SCALE * C[nt][2] + rbB, SCALE * C[nt][3] + rbB);
        *(float2*)(g_impact + (size_t)mA * Gg + n) = v0;
        *(float2*)(g_impact + (size_t)(mA + 8) * Gg + n) = v1;
    }
}

// ---- select: radix rank-200 on screen, gather candidates >= T - MARGIN ----
__global__ void select_kernel() {
    int row = blockIdx.x, t = threadIdx.x;
    const float* vals = g_impact + (size_t)row * Gg;
    __shared__ unsigned int hist[256];
    __shared__ unsigned int sh_prefix;
    __shared__ int sh_r;
    __shared__ int cnt;
    if (t == 0) { sh_prefix = 0u; sh_r = TOPKN; cnt = 0; }
    __syncthreads();
    for (int pass = 3; pass >= 0; pass--) {
        hist[t] = 0u;
        __syncthreads();
        unsigned int pmask = (pass == 3) ? 0u : (0xFFFFFFFFu << ((pass + 1) * 8));
        unsigned int prefix = sh_prefix;
        for (int g = t; g < Gg; g += 256) {
            unsigned int key = fkey(vals[g]);
            if ((key & pmask) == prefix) atomicAdd(&hist[(key >> (pass * 8)) & 0xFF], 1u);
        }
        __syncthreads();
        if (t == 0) {
            int r = sh_r;
            for (int b = 255; b >= 0; b--) {
                int h = (int)hist[b];
                if (r > h) r -= h;
                else { sh_prefix = prefix | ((unsigned int)b << (pass * 8)); sh_r = r; break; }
            }
        }
        __syncthreads();
    }
    float thresh = fkey_inv(sh_prefix) - MARGIN;
    for (int g = t; g < Gg; g += 256) {
        if (vals[g] >= thresh) {
            int pos = atomicAdd(&cnt, 1);
            if (pos < KMAX) g_cand[row * KMAX + pos] = g;
        }
    }
    __syncthreads();
    if (t == 0) g_ncand[row] = cnt < KMAX ? cnt : KMAX;
}

// ---- exact rescore: fp32 dot per candidate (warp-per-candidate) ----
__global__ void __launch_bounds__(256) rescore_kernel(const float* __restrict__ Bg) {
    __shared__ float q[KD];
    int row = blockIdx.x, t = threadIdx.x, lane = t & 31, wid = t >> 5;
    const float* qrow = g_Q2 + (size_t)row * KD;
    for (int i = t; i < KD / 4; i += 256)
        *(float4*)(q + i * 4) = *(const float4*)(qrow + i * 4);
    __syncthreads();
    int nc = g_ncand[row];
    float rb = g_rowbias[row];
    for (int slot = wid; slot < nc; slot += 8) {
        int g = g_cand[row * KMAX + slot];
        const float4* b4 = (const float4*)(Bg + (size_t)g * KD);
        float acc = 0.f;
        for (int i = lane; i < KD / 4; i += 32) {
            float4 bb = b4[i];
            float4 qq = *(const float4*)(q + i * 4);
            acc = fmaf(qq.x, bb.x, acc);
            acc = fmaf(qq.y, bb.y, acc);
            acc = fmaf(qq.z, bb.z, acc);
            acc = fmaf(qq.w, bb.w, acc);
        }
        #pragma unroll
        for (int o = 16; o > 0; o >>= 1) acc += __shfl_xor_sync(0xFFFFFFFFu, acc, o);
        if (lane == 0) g_exval[row * KMAX + slot] = SCALE * acc + rb;
    }
}

// ---- final: rank candidates by exact value, zero-fill, scatter top-200 ----
__global__ void final_kernel(float* __restrict__ out) {
    __shared__ int sidx[KMAX];
    __shared__ unsigned int skey[KMAX];
    __shared__ float sval[KMAX];
    int row = blockIdx.x, t = threadIdx.x;
    int nc = g_ncand[row];
    for (int i = t; i < nc; i += 256) {
        sidx[i] = g_cand[row * KMAX + i];
        float v = g_exval[row * KMAX + i];
        sval[i] = v;
        skey[i] = fkey(v);
    }
    float* orow = out + (size_t)row * Gg;
    for (int g = t; g < Gg; g += 256) orow[g] = 0.f;
    __syncthreads();
    for (int i = t; i < nc; i += 256) {
        unsigned int ki = skey[i]; int xi = sidx[i];
        int rank = 0;
        for (int j = 0; j < nc; j++) {
            unsigned int kj = skey[j];
            if (kj > ki || (kj == ki && sidx[j] < xi)) rank++;
        }
        if (rank < TOPKN) orow[xi] = sval[i];
    }
}

extern "C" void kernel_launch(void* const* d_in, const int* in_sizes, int n_in,
                              void* d_out, int out_size) {
    const float* ctxQ   = (const float*)d_in[0];
    const float* genome = (const float*)d_in[1];
    const float* conf   = (const float*)d_in[2];
    const float* Wq     = (const float*)d_in[3];
    const float* bq     = (const float*)d_in[4];
    const float* Wk     = (const float*)d_in[5];
    const float* bk     = (const float*)d_in[6];
    const float* fw     = (const float*)d_in[7];
    float* out = (float*)d_out;

    int write_w = (out_size >= BP * Gg + Kk) ? 1 : 0;

    preprv_kernel<<<13, 256>>>(conf, fw, bq, bk, Wq, Wk, out + (size_t)BP * Gg, write_w);
    gemm_M_kernel<<<dim3(12, 12), 256>>>(Wq, Wk);
    gemm_Q2_kernel<<<dim3(12, 32), 256>>>(ctxQ);
    qb_kernel<<<256, 256>>>(ctxQ);
    rowbias_kernel<<<1, 256>>>();
    screen_gemm<<<dim3(4, NTILE_N), 256, SMEM_SCREEN>>>(genome);
    select_kernel<<<256, 256>>>();
    rescore_kernel<<<256, 256>>>(genome);
    final_kernel<<<256, 256>>>(out);
}

// round 15
// speedup vs baseline: 1.7166x; 1.7166x over previous
#include <cuda_runtime.h>
#include <cuda_fp16.h>
#include <cstdint>

#define Kk 8
#define Dd 768
#define Gg 20000
#define TOPKN 200
#define BP 256
#define NROW 2048
#define KD 6144
#define SCALE 0.03608439182435161f

// screen GEMM tiling: BM=128 x BN=160 (125*160 = 20000 exactly), 256 threads
#define BM 128
#define BN 160
#define NTILE_N 125
#define NCHUNK 192          // KD/32
// smem: stage = Ah 8K | Bh 10K = 18432B, double buffered
#define OFF_BHS 8192
#define STG_S 18432
#define SMEM_SCREEN (2 * STG_S)

#define KMAX 1024
#define MARGIN 0.012f

__device__ float g_w[Kk];
__device__ float g_cb[BP];
__device__ float g_bqbk;
__device__ float g_r[Dd];
__device__ float g_v[Dd];
__device__ float g_M[Dd * Dd];
__device__ float g_Q2[NROW * Dd];
__device__ __half g_Ah[NROW * Dd];       // f16 hi-split of Q2 (written by gemm_Q2)
__device__ float g_qb[NROW];
__device__ float g_rowbias[BP];
__device__ float g_impact[BP * Gg];      // screen values
__device__ int   g_cand[BP * KMAX];
__device__ int   g_ncand[BP];
__device__ float g_exval[BP * KMAX];

// ---------------- helpers ----------------
__device__ __forceinline__ uint32_t smem_u32(const void* p) {
    uint32_t a;
    asm("{ .reg .u64 t; cvta.to.shared.u64 t, %1; cvt.u32.u64 %0, t; }" : "=r"(a) : "l"(p));
    return a;
}
__device__ __forceinline__ void ldsm4(uint32_t* r, uint32_t a) {
    asm volatile("ldmatrix.sync.aligned.m8n8.x4.shared.b16 {%0,%1,%2,%3}, [%4];"
                 : "=r"(r[0]), "=r"(r[1]), "=r"(r[2]), "=r"(r[3]) : "r"(a));
}
__device__ __forceinline__ void mma16816(float* c, const uint32_t* a, const uint32_t* b) {
    asm volatile("mma.sync.aligned.m16n8k16.row.col.f32.f16.f16.f32 "
                 "{%0,%1,%2,%3}, {%4,%5,%6,%7}, {%8,%9}, {%0,%1,%2,%3};"
                 : "+f"(c[0]), "+f"(c[1]), "+f"(c[2]), "+f"(c[3])
                 : "r"(a[0]), "r"(a[1]), "r"(a[2]), "r"(a[3]), "r"(b[0]), "r"(b[1]));
}
// convert fp32x4 -> hi f16 pairs only, one 8B smem store
__device__ __forceinline__ void cvt_sts_hi(float4 f, uint32_t addr) {
    __half2 h01 = __floats2half2_rn(f.x, f.y);
    __half2 h23 = __floats2half2_rn(f.z, f.w);
    uint32_t h0 = *(uint32_t*)&h01, h1 = *(uint32_t*)&h23;
    asm volatile("st.shared.v2.b32 [%0], {%1,%2};" :: "r"(addr), "r"(h0), "r"(h1) : "memory");
}
__device__ __forceinline__ void sts_u2(uint2 v, uint32_t addr) {
    asm volatile("st.shared.v2.b32 [%0], {%1,%2};" :: "r"(addr), "r"(v.x), "r"(v.y) : "memory");
}
__device__ __forceinline__ unsigned int fkey(float v) {
    unsigned int u = __float_as_uint(v);
    return (u & 0x80000000u) ? ~u : (u | 0x80000000u);
}
__device__ __forceinline__ float fkey_inv(unsigned int k) {
    return (k & 0x80000000u) ? __uint_as_float(k ^ 0x80000000u) : __uint_as_float(~k);
}

// ---- merged prep + rv ----
__global__ void preprv_kernel(const float* __restrict__ conf, const float* __restrict__ fw,
                              const float* __restrict__ bq, const float* __restrict__ bk,
                              const float* __restrict__ Wq, const float* __restrict__ Wk,
                              float* __restrict__ out_w, int write_w) {
    int t = threadIdx.x;
    if (blockIdx.x < 12) {
        if (t < 128) {
            int idx = blockIdx.x * 128 + t;
            if (idx < Dd) {
                float s = 0.f;
                for (int e = 0; e < Dd; e++) s += bq[e] * Wk[e * Dd + idx];
                g_r[idx] = s;
            } else {
                int c = idx - Dd;
                float s = 0.f;
                for (int e = 0; e < Dd; e++) s += Wq[e * Dd + c] * bk[e];
                g_v[c] = s;
            }
        }
        return;
    }
    __shared__ float sw[Kk];
    __shared__ float red[256];
    if (t == 0) {
        float mx = fw[0];
        for (int k = 1; k < Kk; k++) mx = fmaxf(mx, fw[k]);
        float e[Kk]; float s = 0.f;
        for (int k = 0; k < Kk; k++) { e[k] = expf(fw[k] - mx); s += e[k]; }
        for (int k = 0; k < Kk; k++) { sw[k] = e[k] / s; g_w[k] = sw[k]; }
    }
    __syncthreads();
    float p = 0.f;
    for (int i = t; i < Dd; i += 256) p += bq[i] * bk[i];
    red[t] = p; __syncthreads();
    for (int o = 128; o > 0; o >>= 1) { if (t < o) red[t] += red[t + o]; __syncthreads(); }
    if (t == 0) g_bqbk = red[0];
    float cb = 0.f;
    for (int k = 0; k < Kk; k++) {
        float c = fmaxf(conf[t * Kk + k], 1e-6f);
        cb += logf(c) * sw[k];
    }
    g_cb[t] = cb;
    if (write_w && t < Kk) out_w[t] = sw[t];
}

// ---- M = Wq^T @ Wk ----
__global__ void __launch_bounds__(256) gemm_M_kernel(const float* __restrict__ Wq,
                                                     const float* __restrict__ Wk) {
    __shared__ float As[16][64];
    __shared__ float Bs[16][64];
    int t = threadIdx.x;
    int d0 = blockIdx.x * 64, c0 = blockIdx.y * 64;
    int tx = t & 15, ty = t >> 4;
    float hi[4][4];
    #pragma unroll
    for (int i = 0; i < 4; i++)
        #pragma unroll
        for (int j = 0; j < 4; j++) hi[i][j] = 0.f;
    int lkk = (t * 4) >> 6, lm = (t * 4) & 63;
    for (int e0 = 0; e0 < Dd; e0 += 16) {
        float4 a = *(const float4*)(Wq + (e0 + lkk) * Dd + c0 + lm);
        float4 b = *(const float4*)(Wk + (e0 + lkk) * Dd + d0 + lm);
        __syncthreads();
        *(float4*)&As[lkk][lm] = a;
        *(float4*)&Bs[lkk][lm] = b;
        __syncthreads();
        float tv[4][4];
        #pragma unroll
        for (int i = 0; i < 4; i++)
            #pragma unroll
            for (int j = 0; j < 4; j++) tv[i][j] = 0.f;
        #pragma unroll
        for (int kk = 0; kk < 16; kk++) {
            float4 av = *(const float4*)&As[kk][ty * 4];
            float4 bv = *(const float4*)&Bs[kk][tx * 4];
            float am[4] = {av.x, av.y, av.z, av.w};
            float bn[4] = {bv.x, bv.y, bv.z, bv.w};
            #pragma unroll
            for (int i = 0; i < 4; i++)
                #pragma unroll
                for (int j = 0; j < 4; j++) tv[i][j] = fmaf(am[i], bn[j], tv[i][j]);
        }
        #pragma unroll
        for (int i = 0; i < 4; i++)
            #pragma unroll
            for (int j = 0; j < 4; j++) hi[i][j] += tv[i][j];
    }
    #pragma unroll
    for (int i = 0; i < 4; i++)
        #pragma unroll
        for (int j = 0; j < 4; j++)
            g_M[(c0 + ty * 4 + i) * Dd + d0 + tx * 4 + j] = hi[i][j];
}

// ---- Q2 = w_k * (ctxQ @ M + r); also writes f16 hi-split for the screen ----
__global__ void __launch_bounds__(256) gemm_Q2_kernel(const float* __restrict__ ctxQ) {
    __shared__ float As[16][68];
    __shared__ float Bs[16][64];
    int t = threadIdx.x;
    int d0 = blockIdx.x * 64, m0 = blockIdx.y * 64;
    int tx = t & 15, ty = t >> 4;
    float hi[4][4];
    #pragma unroll
    for (int i = 0; i < 4; i++)
        #pragma unroll
        for (int j = 0; j < 4; j++) hi[i][j] = 0.f;
    int alm = (t * 4) >> 4;
    int akk = (t * 4) & 15;
    int bkk = (t * 4) >> 6, bn = (t * 4) & 63;
    for (int e0 = 0; e0 < Dd; e0 += 16) {
        float4 a = *(const float4*)(ctxQ + (m0 + alm) * Dd + e0 + akk);
        float4 b = *(const float4*)(g_M + (e0 + bkk) * Dd + d0 + bn);
        __syncthreads();
        As[akk + 0][alm] = a.x; As[akk + 1][alm] = a.y;
        As[akk + 2][alm] = a.z; As[akk + 3][alm] = a.w;
        *(float4*)&Bs[bkk][bn] = b;
        __syncthreads();
        float tv[4][4];
        #pragma unroll
        for (int i = 0; i < 4; i++)
            #pragma unroll
            for (int j = 0; j < 4; j++) tv[i][j] = 0.f;
        #pragma unroll
        for (int kk = 0; kk < 16; kk++) {
            float4 av = *(const float4*)&As[kk][ty * 4];
            float4 bv = *(const float4*)&Bs[kk][tx * 4];
            float am[4] = {av.x, av.y, av.z, av.w};
            float bn2[4] = {bv.x, bv.y, bv.z, bv.w};
            #pragma unroll
            for (int i = 0; i < 4; i++)
                #pragma unroll
                for (int j = 0; j < 4; j++) tv[i][j] = fmaf(am[i], bn2[j], tv[i][j]);
        }
        #pragma unroll
        for (int i = 0; i < 4; i++)
            #pragma unroll
            for (int j = 0; j < 4; j++) hi[i][j] += tv[i][j];
    }
    #pragma unroll
    for (int i = 0; i < 4; i++) {
        int m = m0 + ty * 4 + i;
        float wk = g_w[m & 7];
        #pragma unroll
        for (int j = 0; j < 4; j++) {
            int d = d0 + tx * 4 + j;
            float v = wk * (hi[i][j] + g_r[d]);
            g_Q2[m * Dd + d] = v;
            g_Ah[m * Dd + d] = __float2half_rn(v);
        }
    }
}

__global__ void qb_kernel(const float* __restrict__ ctxQ) {
    int w = (blockIdx.x * blockDim.x + threadIdx.x) >> 5;
    int lane = threadIdx.x & 31;
    if (w >= NROW) return;
    const float* rowp = ctxQ + w * Dd;
    float s = 0.f;
    for (int c = lane; c < Dd; c += 32) s += rowp[c] * g_v[c];
    #pragma unroll
    for (int o = 16; o > 0; o >>= 1) s += __shfl_xor_sync(0xFFFFFFFFu, s, o);
    if (lane == 0) g_qb[w] = g_w[w & 7] * (s + g_bqbk);
}

__global__ void rowbias_kernel() {
    int t = threadIdx.x;
    if (t < BP) {
        float s = 0.f;
        for (int k = 0; k < Kk; k++) s += g_qb[t * Kk + k];
        g_rowbias[t] = g_cb[t] + SCALE * s;
    }
}

// ---- screen GEMM: hh product only; A pre-split (pure copy), B converted in-loop.
// STS for the next stage issued BETWEEN ks0-LDSM and ks0-MMA so the barrier's
// STS-drain overlaps ~1280 cyc of HMMA issue instead of stalling at the chunk
// tail. Per-(m,n) HMMA order (ks0 then ks1, same nt/mt sequence) unchanged ->
// bit-identical screen values to R13.
__global__ void __launch_bounds__(256, 1) screen_gemm(const float* __restrict__ Bg) {
    extern __shared__ char smem[];
    uint32_t sb = smem_u32(smem);
    int t = threadIdx.x, lane = t & 31, wid = t >> 5;
    int wr = wid & 3, wc = wid >> 2;      // warp tile: 32 m x 80 n
    int m0 = blockIdx.x * BM, n0 = blockIdx.y * BN;

    uint32_t offA[2][2], offB[5][2];
    #pragma unroll
    for (int mt = 0; mt < 2; mt++)
        #pragma unroll
        for (int ks = 0; ks < 2; ks++) {
            int r = wr * 32 + mt * 16 + (lane & 15);
            int u = ks * 2 + (lane >> 4);
            offA[mt][ks] = r * 64 + ((u ^ ((r >> 1) & 3)) << 4);
        }
    #pragma unroll
    for (int ng = 0; ng < 5; ng++)
        #pragma unroll
        for (int ks = 0; ks < 2; ks++) {
            int r = wc * 80 + ng * 16 + (lane & 7) + ((lane >> 4) << 3);
            int u = ks * 2 + ((lane >> 3) & 1);
            offB[ng][ks] = r * 64 + ((u ^ ((r >> 1) & 3)) << 4);
        }

    float C[2][10][4];
    #pragma unroll
    for (int i = 0; i < 2; i++)
        #pragma unroll
        for (int j = 0; j < 10; j++)
            #pragma unroll
            for (int q = 0; q < 4; q++) C[i][j][q] = 0.f;

    int arow = t >> 1, akh = t & 1;
    int brow2 = 128 + (t >> 1);
    bool has2 = (t < 64);
    const __half* pA = g_Ah + (size_t)(m0 / BM) * (BM * KD) + (size_t)arow * KD + akh * 16;
    const float* pB = Bg + (size_t)(n0 + arow) * KD + akh * 16;
    const float* pB2 = Bg + (size_t)(n0 + (has2 ? brow2 : 128)) * KD + akh * 16;
    uint32_t stA[4], stB2[4];
    #pragma unroll
    for (int i = 0; i < 4; i++) {
        int klo = akh * 16 + i * 4;
        stA[i] = (uint32_t)arow * 64 + (((klo >> 3) ^ ((arow >> 1) & 3)) << 4) + (klo & 7) * 2;
        stB2[i] = (uint32_t)brow2 * 64 + (((klo >> 3) ^ ((brow2 >> 1) & 3)) << 4) + (klo & 7) * 2;
    }

    uint2 pvA[4];
    float4 pvB[4], pvB2[4];
#define SLOADC(s) { \
    _Pragma("unroll") \
    for (int i = 0; i < 4; i++) { \
        pvA[i] = *(const uint2*)(pA + (s) * 32 + i * 4); \
        pvB[i] = *(const float4*)(pB + (s) * 32 + i * 4); \
        if (has2) pvB2[i] = *(const float4*)(pB2 + (s) * 32 + i * 4); \
    } }
#define SCVTST(stg) { \
    uint32_t base_ = sb + (stg) * STG_S; \
    _Pragma("unroll") \
    for (int i = 0; i < 4; i++) { \
        sts_u2(pvA[i], base_ + stA[i]); \
        cvt_sts_hi(pvB[i], base_ + OFF_BHS + stA[i]); \
    } \
    if (has2) { \
        _Pragma("unroll") \
        for (int i = 0; i < 4; i++) \
            cvt_sts_hi(pvB2[i], base_ + OFF_BHS + stB2[i]); \
    } }

    SLOADC(0);
    SCVTST(0);
    SLOADC(1);
    __syncthreads();

    #pragma unroll 1
    for (int s = 0; s < NCHUNK; s++) {
        int cur = s & 1;
        uint32_t base = sb + cur * STG_S;
        // ---- ks=0: LDSM ----
        uint32_t ah0[2][4], bh0[10][2];
        #pragma unroll
        for (int mt = 0; mt < 2; mt++) ldsm4(ah0[mt], base + offA[mt][0]);
        #pragma unroll
        for (int ng = 0; ng < 5; ng++) {
            uint32_t rr[4];
            ldsm4(rr, base + OFF_BHS + offB[ng][0]);
            bh0[2 * ng][0] = rr[0]; bh0[2 * ng][1] = rr[1];
            bh0[2 * ng + 1][0] = rr[2]; bh0[2 * ng + 1][1] = rr[3];
        }
        // ---- early STS to other stage + prefetch loads (drain under MMA) ----
        if (s < NCHUNK - 1) {
            SCVTST(1 - cur);
            if (s < NCHUNK - 2) SLOADC(s + 2);
        }
        // ---- ks=0: MMA ----
        #pragma unroll
        for (int nt = 0; nt < 10; nt++)
            #pragma unroll
            for (int mt = 0; mt < 2; mt++) mma16816(C[mt][nt], ah0[mt], bh0[nt]);
        // ---- ks=1: LDSM + MMA ----
        {
            uint32_t ah1[2][4], bh1[10][2];
            #pragma unroll
            for (int mt = 0; mt < 2; mt++) ldsm4(ah1[mt], base + offA[mt][1]);
            #pragma unroll
            for (int ng = 0; ng < 5; ng++) {
                uint32_t rr[4];
                ldsm4(rr, base + OFF_BHS + offB[ng][1]);
                bh1[2 * ng][0] = rr[0]; bh1[2 * ng][1] = rr[1];
                bh1[2 * ng + 1][0] = rr[2]; bh1[2 * ng + 1][1] = rr[3];
            }
            #pragma unroll
            for (int nt = 0; nt < 10; nt++)
                #pragma unroll
                for (int mt = 0; mt < 2; mt++) mma16816(C[mt][nt], ah1[mt], bh1[nt]);
        }
        __syncthreads();
    }

    int gid = lane >> 2, tig = lane & 3;
    #pragma unroll
    for (int mt = 0; mt < 2; mt++) {
        int mA = m0 + wr * 32 + mt * 16 + gid;
        float rbA = g_rowbias[mA];
        float rbB = g_rowbias[mA + 8];
        #pragma unroll
        for (int nt = 0; nt < 10; nt++) {
            int n = n0 + wc * 80 + nt * 8 + tig * 2;
            float2 v0 = make_float2(SCALE * C[mt][nt][0] + rbA, SCALE * C[mt][nt][1] + rbA);
            float2 v1 = make_float2(SCALE * C[mt][nt][2] + rbB, SCALE * C[mt][nt][3] + rbB);
            *(float2*)(g_impact + (size_t)mA * Gg + n) = v0;
            *(float2*)(g_impact + (size_t)(mA + 8) * Gg + n) = v1;
        }
    }
}

// ---- select: radix rank-200 on screen, gather candidates >= T - MARGIN ----
__global__ void select_kernel() {
    int row = blockIdx.x, t = threadIdx.x;
    const float* vals = g_impact + (size_t)row * Gg;
    __shared__ unsigned int hist[256];
    __shared__ unsigned int sh_prefix;
    __shared__ int sh_r;
    __shared__ int cnt;
    if (t == 0) { sh_prefix = 0u; sh_r = TOPKN; cnt = 0; }
    __syncthreads();
    for (int pass = 3; pass >= 0; pass--) {
        hist[t] = 0u;
        __syncthreads();
        unsigned int pmask = (pass == 3) ? 0u : (0xFFFFFFFFu << ((pass + 1) * 8));
        unsigned int prefix = sh_prefix;
        for (int g = t; g < Gg; g += 256) {
            unsigned int key = fkey(vals[g]);
            if ((key & pmask) == prefix) atomicAdd(&hist[(key >> (pass * 8)) & 0xFF], 1u);
        }
        __syncthreads();
        if (t == 0) {
            int r = sh_r;
            for (int b = 255; b >= 0; b--) {
                int h = (int)hist[b];
                if (r > h) r -= h;
                else { sh_prefix = prefix | ((unsigned int)b << (pass * 8)); sh_r = r; break; }
            }
        }
        __syncthreads();
    }
    float thresh = fkey_inv(sh_prefix) - MARGIN;
    for (int g = t; g < Gg; g += 256) {
        if (vals[g] >= thresh) {
            int pos = atomicAdd(&cnt, 1);
            if (pos < KMAX) g_cand[row * KMAX + pos] = g;
        }
    }
    __syncthreads();
    if (t == 0) g_ncand[row] = cnt < KMAX ? cnt : KMAX;
}

// ---- exact rescore: fp32 dot per candidate (warp-per-candidate) ----
__global__ void __launch_bounds__(256) rescore_kernel(const float* __restrict__ Bg) {
    __shared__ float q[KD];
    int row = blockIdx.x, t = threadIdx.x, lane = t & 31, wid = t >> 5;
    const float* qrow = g_Q2 + (size_t)row * KD;
    for (int i = t; i < KD / 4; i += 256)
        *(float4*)(q + i * 4) = *(const float4*)(qrow + i * 4);
    __syncthreads();
    int nc = g_ncand[row];
    float rb = g_rowbias[row];
    for (int slot = wid; slot < nc; slot += 8) {
        int g = g_cand[row * KMAX + slot];
        const float4* b4 = (const float4*)(Bg + (size_t)g * KD);
        float acc = 0.f;
        for (int i = lane; i < KD / 4; i += 32) {
            float4 bb = b4[i];
            float4 qq = *(const float4*)(q + i * 4);
            acc = fmaf(qq.x, bb.x, acc);
            acc = fmaf(qq.y, bb.y, acc);
            acc = fmaf(qq.z, bb.z, acc);
            acc = fmaf(qq.w, bb.w, acc);
        }
        #pragma unroll
        for (int o = 16; o > 0; o >>= 1) acc += __shfl_xor_sync(0xFFFFFFFFu, acc, o);
        if (lane == 0) g_exval[row * KMAX + slot] = SCALE * acc + rb;
    }
}

// ---- final: rank candidates by exact value, zero-fill, scatter top-200 ----
__global__ void final_kernel(float* __restrict__ out) {
    __shared__ int sidx[KMAX];
    __shared__ unsigned int skey[KMAX];
    __shared__ float sval[KMAX];
    int row = blockIdx.x, t = threadIdx.x;
    int nc = g_ncand[row];
    for (int i = t; i < nc; i += 256) {
        sidx[i] = g_cand[row * KMAX + i];
        float v = g_exval[row * KMAX + i];
        sval[i] = v;
        skey[i] = fkey(v);
    }
    float* orow = out + (size_t)row * Gg;
    for (int g = t; g < Gg; g += 256) orow[g] = 0.f;
    __syncthreads();
    for (int i = t; i < nc; i += 256) {
        unsigned int ki = skey[i]; int xi = sidx[i];
        int rank = 0;
        for (int j = 0; j < nc; j++) {
            unsigned int kj = skey[j];
            if (kj > ki || (kj == ki && sidx[j] < xi)) rank++;
        }
        if (rank < TOPKN) orow[xi] = sval[i];
    }
}

extern "C" void kernel_launch(void* const* d_in, const int* in_sizes, int n_in,
                              void* d_out, int out_size) {
    const float* ctxQ   = (const float*)d_in[0];
    const float* genome = (const float*)d_in[1];
    const float* conf   = (const float*)d_in[2];
    const float* Wq     = (const float*)d_in[3];
    const float* bq     = (const float*)d_in[4];
    const float* Wk     = (const float*)d_in[5];
    const float* bk     = (const float*)d_in[6];
    const float* fw     = (const float*)d_in[7];
    float* out = (float*)d_out;

    int write_w = (out_size >= BP * Gg + Kk) ? 1 : 0;

    preprv_kernel<<<13, 256>>>(conf, fw, bq, bk, Wq, Wk, out + (size_t)BP * Gg, write_w);
    gemm_M_kernel<<<dim3(12, 12), 256>>>(Wq, Wk);
    gemm_Q2_kernel<<<dim3(12, 32), 256>>>(ctxQ);
    qb_kernel<<<256, 256>>>(ctxQ);
    rowbias_kernel<<<1, 256>>>();
    screen_gemm<<<dim3(2, NTILE_N), 256, SMEM_SCREEN>>>(genome);
    select_kernel<<<256, 256>>>();
    rescore_kernel<<<256, 256>>>(genome);
    final_kernel<<<256, 256>>>(out);
}